// round 12
// baseline (speedup 1.0000x reference)
#include <cuda_runtime.h>
#include <math.h>
#include <stdint.h>

// ---------------------------------------------------------------------------
// Scratch (__device__ globals)
// ---------------------------------------------------------------------------
__device__ float g_om1 [16*147*128*128];
__device__ float g_col1[16*147*128*128];
__device__ float g_t1  [16*64*128*128];
__device__ float g_om2 [16*48*64*64];
__device__ float g_col2[16*1024*64*64];
__device__ float g_t2  [16*128*64*64];
__device__ float g_om3 [16*48*32*32];
__device__ float g_col3[16*2048*32*32];
__device__ float g_t3  [16*256*32*32];
__device__ float g_y   [16*256*32*32];
__device__ float g_cv  [16*256*32*32];
__device__ float g_h   [16*256*32*32];

// ---------------------------------------------------------------------------
// bf16 pack/split helpers
// ---------------------------------------------------------------------------
__device__ __forceinline__ uint32_t pack_bf2(float e0, float e1){
    uint32_t r;  // low half = e0, high half = e1
    asm("cvt.rn.bf16x2.f32 %0, %2, %1;" : "=r"(r) : "f"(e0), "f"(e1));
    return r;
}
__device__ __forceinline__ float bf_lo_f(uint32_t p){ return __uint_as_float(p << 16); }
__device__ __forceinline__ float bf_hi_f(uint32_t p){ return __uint_as_float(p & 0xffff0000u); }

// mma.sync m16n8k16 row.col f32 += bf16*bf16 (sm_80+ baseline PTX -> HMMA)
__device__ __forceinline__ void mma_bf16(float* c, const uint32_t* a,
                                         uint32_t b0, uint32_t b1){
    asm volatile(
        "mma.sync.aligned.m16n8k16.row.col.f32.bf16.bf16.f32 "
        "{%0,%1,%2,%3}, {%4,%5,%6,%7}, {%8,%9}, {%0,%1,%2,%3};"
        : "+f"(c[0]), "+f"(c[1]), "+f"(c[2]), "+f"(c[3])
        : "r"(a[0]), "r"(a[1]), "r"(a[2]), "r"(a[3]), "r"(b0), "r"(b1));
}

// ---------------------------------------------------------------------------
// Conv-as-GEMM via mma.sync bf16, hi/lo split, 3 passes (hi*hi + hi*lo + lo*hi).
// Tile BM(M) x 128(N), K chunk KCH fp32 (KCH/16 ks sub-chunks per barrier).
// 8 warps: 2(m) x 4(n). Fragment-native smem layout: A frags via LDS.128,
// B via LDS.64, conflict-free; frag sets loaded once per ks, reused over passes.
// ---------------------------------------------------------------------------
template<int CIN,int H,int W,int KH,int KW,int STR,int PAD,int HO,int WO,int REFLECT,int BM,int KCH>
__global__ void __launch_bounds__(256, (BM==64) ? 2 : 1)
conv_mma(const float* __restrict__ in, const float* __restrict__ Wt,
         const float* __restrict__ bias, float* __restrict__ out, int M)
{
    constexpr int Kdim = CIN*KH*KW;
    constexpr int HW   = HO*WO;
    constexpr int NT   = (Kdim + KCH - 1)/KCH;
    constexpr int MI   = BM/32;            // mi count per warp
    constexpr int KSN  = KCH/16;           // ks sub-chunks per barrier
    constexpr int SAV  = MI*4 + 4;         // A per-lane stride (u32)
    constexpr int AR   = MI*KSN;           // A producer iters
    constexpr int BR   = 4*KSN;            // B producer iters
    constexpr int EMASK= 4*MI - 1;
    constexpr int ESH  = (MI==4) ? 4 : 3;  // log2(4*MI)
    constexpr int A_U32= 256*KSN*SAV;      // [2buf][2pa][KSN][2wm][32][SAV]

    extern __shared__ __align__(16) uint32_t sm[];
    uint32_t* sBm = sm + A_U32;            // [2buf][2pb][KSN][4wn][32][10]

    const int t    = threadIdx.x;
    const int lane = t & 31;
    const int w8   = t >> 5;
    const int gidl = lane >> 2;
    const int tidl = lane & 3;
    const int g4   = lane >> 3;            // A store bank-shift group
    const int g2   = lane >> 4;            // B store bank-shift group

    const int wid = w8;
    const int wm  = wid & 1;
    const int wn  = wid >> 1;
    const int mb  = wm*(BM/2);
    const int nb  = wn*32;

    const int nTile = blockIdx.x * 128;
    const int mTile = blockIdx.y * BM;

    auto aOff = [&](int buf,int pa,int ks,int wmi,int ln,int e)->int{
        return ((((buf*2+pa)*KSN+ks)*2+wmi)*32 + ln)*SAV + e;
    };
    auto bOff = [&](int buf,int pb,int ks,int wni,int ln,int e)->int{
        return ((((buf*2+pb)*KSN+ks)*4+wni)*32 + ln)*10 + e;
    };

    auto gatherB = [&](int n, int k)->float{
        if (k >= Kdim) return 0.f;
        const int b   = n / HW;
        const int rem = n % HW;
        const int oy  = rem / WO;
        const int ox  = rem % WO;
        const int ci  = k / (KH*KW);
        const int r   = k % (KH*KW);
        const int ky  = r / KW;
        const int kx  = r % KW;
        int iy = oy*STR - PAD + ky;
        int ix = ox*STR - PAD + kx;
        const float* inb = in + (size_t)b*CIN*H*W;
        if (REFLECT) {
            iy = iy < 0 ? -iy : (iy >= H ? 2*H-2-iy : iy);
            ix = ix < 0 ? -ix : (ix >= W ? 2*W-2-ix : ix);
            return inb[((size_t)ci*H + iy)*W + ix];
        }
        if (iy >= 0 && iy < H && ix >= 0 && ix < W)
            return inb[((size_t)ci*H + iy)*W + ix];
        return 0.f;
    };

    float fa[2*AR], fb[2*BR];

    auto loadA = [&](int k0){
        #pragma unroll
        for (int i = 0; i < AR; i++) {
            const int v   = i*8 + w8;
            const int elt = (v + g4) & EMASK;
            const int wm_ = (v >> ESH) & 1;
            const int mi_ = elt >> 2;
            const int j   = elt & 3;
            const int m   = wm_*(BM/2) + mi_*16 + (j & 1)*8 + gidl;
            const int kp  = (v >> (ESH+1))*8 + (j >> 1)*4 + tidl;
            const int gm  = mTile + m;
            const int k   = k0 + kp*2;
            const bool mv = (gm < M);
            const float* row = Wt + (size_t)gm * (size_t)Kdim;
            fa[2*i]   = (mv && k     < Kdim) ? row[k]   : 0.f;
            fa[2*i+1] = (mv && k + 1 < Kdim) ? row[k+1] : 0.f;
        }
    };
    auto loadB = [&](int k0){
        #pragma unroll
        for (int i = 0; i < BR; i++) {
            const int v   = i*8 + w8;
            const int ni2 = ((v & 7) + g2) & 7;
            const int wn_ = (v >> 3) & 3;
            const int ks_ = v >> 5;
            const int n   = nTile + wn_*32 + (ni2 >> 1)*8 + gidl;
            const int kp  = ks_*8 + (ni2 & 1)*4 + tidl;
            const int k   = k0 + kp*2;
            fb[2*i]   = gatherB(n, k);
            fb[2*i+1] = gatherB(n, k+1);
        }
    };
    auto storeAB = [&](int buf){
        #pragma unroll
        for (int i = 0; i < AR; i++) {
            const int v   = i*8 + w8;
            const int elt = (v + g4) & EMASK;
            const int wm_ = (v >> ESH) & 1;
            const int ks_ = v >> (ESH+1);
            const uint32_t h = pack_bf2(fa[2*i], fa[2*i+1]);
            const uint32_t l = pack_bf2(fa[2*i]   - bf_lo_f(h),
                                        fa[2*i+1] - bf_hi_f(h));
            sm[aOff(buf,0,ks_,wm_,lane,elt)] = h;
            sm[aOff(buf,1,ks_,wm_,lane,elt)] = l;
        }
        #pragma unroll
        for (int i = 0; i < BR; i++) {
            const int v   = i*8 + w8;
            const int ni2 = ((v & 7) + g2) & 7;
            const int wn_ = (v >> 3) & 3;
            const int ks_ = v >> 5;
            const uint32_t h = pack_bf2(fb[2*i], fb[2*i+1]);
            const uint32_t l = pack_bf2(fb[2*i]   - bf_lo_f(h),
                                        fb[2*i+1] - bf_hi_f(h));
            sBm[bOff(buf,0,ks_,wn_,lane,ni2)] = h;
            sBm[bOff(buf,1,ks_,wn_,lane,ni2)] = l;
        }
    };

    float acc[MI][4][4];
    #pragma unroll
    for (int mi = 0; mi < MI; mi++)
        #pragma unroll
        for (int ni = 0; ni < 4; ni++)
            #pragma unroll
            for (int c = 0; c < 4; c++) acc[mi][ni][c] = 0.f;

    loadA(0); loadB(0);
    storeAB(0);
    __syncthreads();

    for (int it = 0; it < NT; it++) {
        const int cur  = it & 1;
        const bool more = (it + 1 < NT);
        if (more) { loadA((it+1)*KCH); loadB((it+1)*KCH); }

        #pragma unroll
        for (int ks = 0; ks < KSN; ks++) {
            uint4 afv[2][MI];
            #pragma unroll
            for (int pa = 0; pa < 2; pa++)
                #pragma unroll
                for (int mi = 0; mi < MI; mi++)
                    afv[pa][mi] = *reinterpret_cast<const uint4*>(
                        &sm[aOff(cur,pa,ks,wm,lane,mi*4)]);
            uint2 bvv[2][4];
            #pragma unroll
            for (int pb = 0; pb < 2; pb++)
                #pragma unroll
                for (int ni = 0; ni < 4; ni++)
                    bvv[pb][ni] = *reinterpret_cast<const uint2*>(
                        &sBm[bOff(cur,pb,ks,wn,lane,ni*2)]);

            #pragma unroll
            for (int p = 0; p < 3; p++) {
                const int pa = (p == 2) ? 1 : 0;
                const int pb = (p == 1) ? 1 : 0;
                #pragma unroll
                for (int ni = 0; ni < 4; ni++)
                    #pragma unroll
                    for (int mi = 0; mi < MI; mi++)
                        mma_bf16(acc[mi][ni],
                                 reinterpret_cast<const uint32_t*>(&afv[pa][mi]),
                                 bvv[pb][ni].x, bvv[pb][ni].y);
            }
        }

        if (more) {
            storeAB(cur ^ 1);
            __syncthreads();
        }
    }

    // ---- epilogue: direct register -> gmem (float2 per c-pair) ----
    const int b2   = nTile / HW;
    const int pix0 = nTile % HW;
    #pragma unroll
    for (int mi = 0; mi < MI; mi++) {
        const int r0 = mTile + mb + mi*16 + gidl;
        const int r1 = r0 + 8;
        const bool v0 = (r0 < M);
        const bool v1 = (r1 < M);
        const float bv0 = v0 ? bias[r0] : 0.f;
        const float bv1 = v1 ? bias[r1] : 0.f;
        #pragma unroll
        for (int ni = 0; ni < 4; ni++) {
            const int nloc = nb + ni*8 + tidl*2;
            if (v0) {
                float2 o0 = make_float2(acc[mi][ni][0] + bv0, acc[mi][ni][1] + bv0);
                *reinterpret_cast<float2*>(out + ((size_t)b2*M + r0)*HW + pix0 + nloc) = o0;
            }
            if (v1) {
                float2 o1 = make_float2(acc[mi][ni][2] + bv1, acc[mi][ni][3] + bv1);
                *reinterpret_cast<float2*>(out + ((size_t)b2*M + r1)*HW + pix0 + nloc) = o1;
            }
        }
    }
}

// smem byte size per (BM, KCH)
static constexpr int smemBytes(int BM, int KCH){
    const int SAV = BM/8 + 4;
    const int KSN = KCH/16;
    return (256*KSN*SAV + 5120*KSN) * 4;
}

// ---------------------------------------------------------------------------
// DCNv2 sampling: col[b, ci*K + k, pix] = mask * bilinear(x[b,ci], ys, xs)
// ---------------------------------------------------------------------------
template<int CIN,int H,int W,int KH,int KW,int STR,int PAD,int HO,int WO>
__global__ void __launch_bounds__(256)
deform_sample_kernel(const float* __restrict__ x, const float* __restrict__ om,
                     float* __restrict__ col)
{
    constexpr int B  = 16;
    constexpr int K  = KH*KW;
    constexpr int HW = HO*WO;

    const int idx = blockIdx.x*blockDim.x + threadIdx.x;
    if (idx >= B*K*HW) return;

    const int ox  = idx % WO;
    int tmp       = idx / WO;
    const int oy  = tmp % HO;  tmp /= HO;
    const int k   = tmp % K;
    const int b   = tmp / K;
    const int ky  = k / KW;
    const int kx  = k % KW;

    const int pix = oy*WO + ox;
    const float offy = om[((size_t)(b*3*K + 2*k    )*HW) + pix];
    const float offx = om[((size_t)(b*3*K + 2*k + 1)*HW) + pix];
    const float mv   = om[((size_t)(b*3*K + 2*K + k)*HW) + pix];
    const float mask = 1.f / (1.f + expf(-mv));

    const float ys = (float)(oy*STR - PAD + ky) + offy;
    const float xs = (float)(ox*STR - PAD + kx) + offx;

    const float y0f = floorf(ys), x0f = floorf(xs);
    const float dy = ys - y0f,    dx = xs - x0f;
    const int y0 = (int)y0f, x0 = (int)x0f;
    const int y1 = y0 + 1,   x1 = x0 + 1;

    const bool vy0 = (y0 >= 0) & (y0 < H);
    const bool vy1 = (y1 >= 0) & (y1 < H);
    const bool vx0 = (x0 >= 0) & (x0 < W);
    const bool vx1 = (x1 >= 0) & (x1 < W);

    const int cy0 = min(max(y0, 0), H-1), cy1 = min(max(y1, 0), H-1);
    const int cx0 = min(max(x0, 0), W-1), cx1 = min(max(x1, 0), W-1);

    const float f00 = (vy0 && vx0) ? (1.f-dy)*(1.f-dx)*mask : 0.f;
    const float f01 = (vy0 && vx1) ? (1.f-dy)*dx*mask       : 0.f;
    const float f10 = (vy1 && vx0) ? dy*(1.f-dx)*mask       : 0.f;
    const float f11 = (vy1 && vx1) ? dy*dx*mask             : 0.f;

    const int i00 = cy0*W + cx0, i01 = cy0*W + cx1;
    const int i10 = cy1*W + cx0, i11 = cy1*W + cx1;

    const float* xb = x + (size_t)b*CIN*H*W;
    float* cp = col + (((size_t)b*CIN*K + k)*HW) + pix;

    #pragma unroll 4
    for (int ci = 0; ci < CIN; ci++) {
        const float* img = xb + (size_t)ci*H*W;
        const float v = f00*img[i00] + f01*img[i01] + f10*img[i10] + f11*img[i11];
        cp[(size_t)ci*K*HW] = v;
    }
}

// ---------------------------------------------------------------------------
// Instance norm: single stats pass (sum+sumsq, float4) + write pass.
// ---------------------------------------------------------------------------
__global__ void __launch_bounds__(256)
instnorm_kernel(const float* __restrict__ in, float* __restrict__ out,
                const float* __restrict__ addsrc, int HW, int relu)
{
    const int bc = blockIdx.x;
    const int HW4 = HW >> 2;
    const float4* p4 = reinterpret_cast<const float4*>(in) + (size_t)bc*HW4;
    float4* q4 = reinterpret_cast<float4*>(out) + (size_t)bc*HW4;
    const float4* a4 = addsrc ?
        reinterpret_cast<const float4*>(addsrc) + (size_t)bc*HW4 : nullptr;

    __shared__ float redS[256];
    __shared__ float redQ[256];
    __shared__ float s_mu, s_rs;
    const int t = threadIdx.x;

    float s = 0.f, q = 0.f;
    for (int i = t; i < HW4; i += 256) {
        const float4 v = p4[i];
        s += v.x + v.y + v.z + v.w;
        q += v.x*v.x + v.y*v.y + v.z*v.z + v.w*v.w;
    }
    redS[t] = s; redQ[t] = q; __syncthreads();
    for (int o = 128; o > 0; o >>= 1) {
        if (t < o) { redS[t] += redS[t+o]; redQ[t] += redQ[t+o]; }
        __syncthreads();
    }
    if (t == 0) {
        const float mu = redS[0] / (float)HW;
        float var = redQ[0] / (float)HW - mu*mu;
        var = fmaxf(var, 0.f);
        s_mu = mu;
        s_rs = rsqrtf(var + 1e-5f);
    }
    __syncthreads();
    const float mu = s_mu;
    const float rs = s_rs;

    for (int i = t; i < HW4; i += 256) {
        float4 v = p4[i];
        v.x = (v.x - mu)*rs; v.y = (v.y - mu)*rs;
        v.z = (v.z - mu)*rs; v.w = (v.w - mu)*rs;
        if (relu) {
            v.x = fmaxf(v.x, 0.f); v.y = fmaxf(v.y, 0.f);
            v.z = fmaxf(v.z, 0.f); v.w = fmaxf(v.w, 0.f);
        }
        if (a4) {
            const float4 a = a4[i];
            v.x += a.x; v.y += a.y; v.z += a.z; v.w += a.w;
        }
        q4[i] = v;
    }
}

// ---------------------------------------------------------------------------
// Launch
// ---------------------------------------------------------------------------
extern "C" void kernel_launch(void* const* d_in, const int* in_sizes, int n_in,
                              void* d_out, int out_size)
{
    const float* x      = (const float*)d_in[0];
    const float* w_off1 = (const float*)d_in[1];
    const float* b_off1 = (const float*)d_in[2];
    const float* w1     = (const float*)d_in[3];
    const float* b1     = (const float*)d_in[4];
    const float* w_off2 = (const float*)d_in[5];
    const float* b_off2 = (const float*)d_in[6];
    const float* w2     = (const float*)d_in[7];
    const float* b2     = (const float*)d_in[8];
    const float* w_off3 = (const float*)d_in[9];
    const float* b_off3 = (const float*)d_in[10];
    const float* w3     = (const float*)d_in[11];
    const float* b3     = (const float*)d_in[12];
    const float* rw0a   = (const float*)d_in[13];
    const float* rb0a   = (const float*)d_in[14];
    const float* rw0b   = (const float*)d_in[15];
    const float* rb0b   = (const float*)d_in[16];
    const float* rw1a   = (const float*)d_in[17];
    const float* rb1a   = (const float*)d_in[18];
    const float* rw1b   = (const float*)d_in[19];
    const float* rb1b   = (const float*)d_in[20];

    float* out = (float*)d_out;
    float* out_h  = out;                                   // [16,256,32,32]
    float* out_s2 = out + 16*256*32*32;                    // [16,128,64,64]
    float* out_s3 = out + 16*256*32*32 + 16*128*64*64;     // [16,256,32,32]

    float *om1,*col1,*t1,*om2,*col2,*t2,*om3,*col3,*t3,*ybuf,*cvb,*hbuf;
    cudaGetSymbolAddress((void**)&om1,  g_om1);
    cudaGetSymbolAddress((void**)&col1, g_col1);
    cudaGetSymbolAddress((void**)&t1,   g_t1);
    cudaGetSymbolAddress((void**)&om2,  g_om2);
    cudaGetSymbolAddress((void**)&col2, g_col2);
    cudaGetSymbolAddress((void**)&t2,   g_t2);
    cudaGetSymbolAddress((void**)&om3,  g_om3);
    cudaGetSymbolAddress((void**)&col3, g_col3);
    cudaGetSymbolAddress((void**)&t3,   g_t3);
    cudaGetSymbolAddress((void**)&ybuf, g_y);
    cudaGetSymbolAddress((void**)&cvb,  g_cv);
    cudaGetSymbolAddress((void**)&hbuf, g_h);

    constexpr int S64   = smemBytes(64, 32);    // 65536
    constexpr int S128  = smemBytes(128, 64);   // 163840

    auto setmax = [](const void* f, int bytes){
        cudaFuncSetAttribute(f, cudaFuncAttributeMaxDynamicSharedMemorySize, bytes);
    };
    setmax((const void*)conv_mma<3,128,128,7,7,1,3,128,128,0,64,32>,     S64);
    setmax((const void*)conv_mma<147,128,128,1,1,1,0,128,128,0,64,32>,   S64);
    setmax((const void*)conv_mma<64,128,128,4,4,2,1,64,64,0,64,32>,      S64);
    setmax((const void*)conv_mma<1024,64,64,1,1,1,0,64,64,0,128,64>,     S128);
    setmax((const void*)conv_mma<128,64,64,4,4,2,1,32,32,0,64,32>,       S64);
    setmax((const void*)conv_mma<2048,32,32,1,1,1,0,32,32,0,128,64>,     S128);
    setmax((const void*)conv_mma<256,32,32,3,3,1,1,32,32,1,128,64>,      S128);

    // ------------------ Stage 1: 3 -> 64, 7x7, s1 p3, 128x128 ------------------
    {
        conv_mma<3,128,128,7,7,1,3,128,128,0,64,32>
            <<<dim3(2048, 3), 256, S64>>>(x, w_off1, b_off1, om1, 147);

        const int tot = 16*49*128*128;
        deform_sample_kernel<3,128,128,7,7,1,3,128,128>
            <<<(tot+255)/256, 256>>>(x, om1, col1);

        conv_mma<147,128,128,1,1,1,0,128,128,0,64,32>
            <<<dim3(2048, 1), 256, S64>>>(col1, w1, b1, t1, 64);

        instnorm_kernel<<<16*64, 256>>>(t1, t1, nullptr, 128*128, 1);
    }

    // ------------------ Stage 2: 64 -> 128, 4x4, s2 p1, -> 64x64 ---------------
    {
        conv_mma<64,128,128,4,4,2,1,64,64,0,64,32>
            <<<dim3(512, 1), 256, S64>>>(t1, w_off2, b_off2, om2, 48);

        const int tot = 16*16*64*64;
        deform_sample_kernel<64,128,128,4,4,2,1,64,64>
            <<<(tot+255)/256, 256>>>(t1, om2, col2);

        conv_mma<1024,64,64,1,1,1,0,64,64,0,128,64>
            <<<dim3(512, 1), 256, S128>>>(col2, w2, b2, t2, 128);

        instnorm_kernel<<<16*128, 256>>>(t2, out_s2, nullptr, 64*64, 1);   // skip2
    }

    // ------------------ Stage 3: 128 -> 256, 4x4, s2 p1, -> 32x32 --------------
    {
        conv_mma<128,64,64,4,4,2,1,32,32,0,64,32>
            <<<dim3(128, 1), 256, S64>>>(out_s2, w_off3, b_off3, om3, 48);

        const int tot = 16*16*32*32;
        deform_sample_kernel<128,64,64,4,4,2,1,32,32>
            <<<(tot+255)/256, 256>>>(out_s2, om3, col3);

        conv_mma<2048,32,32,1,1,1,0,32,32,0,128,64>
            <<<dim3(128, 2), 256, S128>>>(col3, w3, b3, t3, 256);

        instnorm_kernel<<<16*256, 256>>>(t3, out_s3, nullptr, 32*32, 1);   // skip3
    }

    // ------------------ Residual blocks on [16,256,32,32] ----------------------
    const dim3 cgrid(128, 2);

    // block 0: input = skip3 (reads d_out region)
    conv_mma<256,32,32,3,3,1,1,32,32,1,128,64><<<cgrid, 256, S128>>>(out_s3, rw0a, rb0a, cvb, 256);
    instnorm_kernel<<<16*256, 256>>>(cvb, ybuf, nullptr, 32*32, 1);
    conv_mma<256,32,32,3,3,1,1,32,32,1,128,64><<<cgrid, 256, S128>>>(ybuf, rw0b, rb0b, cvb, 256);
    instnorm_kernel<<<16*256, 256>>>(cvb, hbuf, out_s3, 32*32, 0);   // h = skip3 + IN(conv)

    // block 1: input = hbuf
    conv_mma<256,32,32,3,3,1,1,32,32,1,128,64><<<cgrid, 256, S128>>>(hbuf, rw1a, rb1a, cvb, 256);
    instnorm_kernel<<<16*256, 256>>>(cvb, ybuf, nullptr, 32*32, 1);
    conv_mma<256,32,32,3,3,1,1,32,32,1,128,64><<<cgrid, 256, S128>>>(ybuf, rw1b, rb1b, cvb, 256);
    instnorm_kernel<<<16*256, 256>>>(cvb, out_h, hbuf, 32*32, 0);    // final h
}

// round 14
// speedup vs baseline: 1.0007x; 1.0007x over previous
#include <cuda_runtime.h>
#include <math.h>
#include <stdint.h>

// ---------------------------------------------------------------------------
// Scratch (__device__ globals)
// ---------------------------------------------------------------------------
__device__ float g_om1 [16*147*128*128];
__device__ float g_col1[16*147*128*128];
__device__ float g_t1  [16*64*128*128];
__device__ float g_om2 [16*48*64*64];
__device__ float g_col2[16*1024*64*64];
__device__ float g_t2  [16*128*64*64];
__device__ float g_om3 [16*48*32*32];
__device__ float g_col3[16*2048*32*32];
__device__ float g_t3  [16*256*32*32];
__device__ float g_y   [16*256*32*32];
__device__ float g_cv  [16*256*32*32];
__device__ float g_h   [16*256*32*32];

// ---------------------------------------------------------------------------
// bf16 pack/split helpers
// ---------------------------------------------------------------------------
__device__ __forceinline__ uint32_t pack_bf2(float e0, float e1){
    uint32_t r;  // low half = e0, high half = e1
    asm("cvt.rn.bf16x2.f32 %0, %2, %1;" : "=r"(r) : "f"(e0), "f"(e1));
    return r;
}
__device__ __forceinline__ float bf_lo_f(uint32_t p){ return __uint_as_float(p << 16); }
__device__ __forceinline__ float bf_hi_f(uint32_t p){ return __uint_as_float(p & 0xffff0000u); }

// mma.sync m16n8k16 row.col f32 += bf16*bf16 (sm_80+ baseline PTX -> HMMA)
__device__ __forceinline__ void mma_bf16(float* c, const uint32_t* a,
                                         uint32_t b0, uint32_t b1){
    asm volatile(
        "mma.sync.aligned.m16n8k16.row.col.f32.bf16.bf16.f32 "
        "{%0,%1,%2,%3}, {%4,%5,%6,%7}, {%8,%9}, {%0,%1,%2,%3};"
        : "+f"(c[0]), "+f"(c[1]), "+f"(c[2]), "+f"(c[3])
        : "r"(a[0]), "r"(a[1]), "r"(a[2]), "r"(a[3]), "r"(b0), "r"(b1));
}

// ---------------------------------------------------------------------------
// Conv-as-GEMM via mma.sync bf16, hi/lo split, 3 passes (hi*hi + hi*lo + lo*hi).
// Tile BM(M) x 128(N), K chunk 32 fp32. 8 warps: 2(m) x 4(n).
// Fragment-native smem layout: A frags read via LDS.128, B via LDS.64,
// conflict-free both sides; frag sets loaded once per ks, reused over passes.
// ---------------------------------------------------------------------------
template<int CIN,int H,int W,int KH,int KW,int STR,int PAD,int HO,int WO,int REFLECT,int BM>
__global__ void __launch_bounds__(256, (BM==64) ? 2 : 1)
conv_mma(const float* __restrict__ in, const float* __restrict__ Wt,
         const float* __restrict__ bias, float* __restrict__ out, int M)
{
    constexpr int Kdim = CIN*KH*KW;
    constexpr int HW   = HO*WO;
    constexpr int BK   = 32;
    constexpr int NT   = (Kdim + BK - 1)/BK;
    constexpr int MI   = BM/32;            // mi count per warp
    constexpr int SAV  = MI*4 + 4;         // A per-lane stride (u32): odd mult of 16B
    constexpr int AR   = BM/16;            // A producer iters
    constexpr int EMASK= 4*MI - 1;
    constexpr int ESH  = (MI==4) ? 4 : 3;  // log2(4*MI)
    constexpr int A_U32= 512*SAV;          // [2buf][2pa][2ks][2wm][32][SAV]

    extern __shared__ __align__(16) uint32_t sm[];
    uint32_t* sBm = sm + A_U32;            // [2buf][2pb][2ks][4wn][32][10]

    const int t    = threadIdx.x;
    const int lane = t & 31;
    const int w8   = t >> 5;
    const int gidl = lane >> 2;
    const int tidl = lane & 3;
    const int g4   = lane >> 3;            // A store bank-shift group
    const int g2   = lane >> 4;            // B store bank-shift group

    const int wid = w8;
    const int wm  = wid & 1;
    const int wn  = wid >> 1;
    const int mb  = wm*(BM/2);
    const int nb  = wn*32;

    const int nTile = blockIdx.x * 128;
    const int mTile = blockIdx.y * BM;

    auto aOff = [&](int buf,int pa,int ks,int wmi,int ln,int e)->int{
        return ((((buf*2+pa)*2+ks)*2+wmi)*32 + ln)*SAV + e;
    };
    auto bOff = [&](int buf,int pb,int ks,int wni,int ln,int e)->int{
        return ((((buf*2+pb)*2+ks)*4+wni)*32 + ln)*10 + e;
    };

    auto gatherB = [&](int n, int k)->float{
        if (k >= Kdim) return 0.f;
        const int b   = n / HW;
        const int rem = n % HW;
        const int oy  = rem / WO;
        const int ox  = rem % WO;
        const int ci  = k / (KH*KW);
        const int r   = k % (KH*KW);
        const int ky  = r / KW;
        const int kx  = r % KW;
        int iy = oy*STR - PAD + ky;
        int ix = ox*STR - PAD + kx;
        const float* inb = in + (size_t)b*CIN*H*W;
        if (REFLECT) {
            iy = iy < 0 ? -iy : (iy >= H ? 2*H-2-iy : iy);
            ix = ix < 0 ? -ix : (ix >= W ? 2*W-2-ix : ix);
            return inb[((size_t)ci*H + iy)*W + ix];
        }
        if (iy >= 0 && iy < H && ix >= 0 && ix < W)
            return inb[((size_t)ci*H + iy)*W + ix];
        return 0.f;
    };

    float fa[2*AR], fb[16];

    auto loadA = [&](int k0){
        #pragma unroll
        for (int i = 0; i < AR; i++) {
            const int v   = i*8 + w8;
            const int elt = (v + g4) & EMASK;
            const int wm_ = (v >> ESH) & 1;
            const int mi_ = elt >> 2;
            const int j   = elt & 3;
            const int m   = wm_*(BM/2) + mi_*16 + (j & 1)*8 + gidl;
            const int kp  = (v >> (ESH+1))*8 + (j >> 1)*4 + tidl;
            const int gm  = mTile + m;
            const int k   = k0 + kp*2;
            const bool mv = (gm < M);
            const float* row = Wt + (size_t)gm * (size_t)Kdim;
            fa[2*i]   = (mv && k     < Kdim) ? row[k]   : 0.f;
            fa[2*i+1] = (mv && k + 1 < Kdim) ? row[k+1] : 0.f;
        }
    };
    auto loadB = [&](int k0){
        #pragma unroll
        for (int i = 0; i < 8; i++) {
            const int v   = i*8 + w8;
            const int ni2 = ((v & 7) + g2) & 7;
            const int wn_ = (v >> 3) & 3;
            const int ks_ = v >> 5;
            const int n   = nTile + wn_*32 + (ni2 >> 1)*8 + gidl;
            const int kp  = ks_*8 + (ni2 & 1)*4 + tidl;
            const int k   = k0 + kp*2;
            fb[2*i]   = gatherB(n, k);
            fb[2*i+1] = gatherB(n, k+1);
        }
    };
    auto storeAB = [&](int buf){
        #pragma unroll
        for (int i = 0; i < AR; i++) {
            const int v   = i*8 + w8;
            const int elt = (v + g4) & EMASK;
            const int wm_ = (v >> ESH) & 1;
            const int ks_ = v >> (ESH+1);
            const uint32_t h = pack_bf2(fa[2*i], fa[2*i+1]);
            const uint32_t l = pack_bf2(fa[2*i]   - bf_lo_f(h),
                                        fa[2*i+1] - bf_hi_f(h));
            sm[aOff(buf,0,ks_,wm_,lane,elt)] = h;
            sm[aOff(buf,1,ks_,wm_,lane,elt)] = l;
        }
        #pragma unroll
        for (int i = 0; i < 8; i++) {
            const int v   = i*8 + w8;
            const int ni2 = ((v & 7) + g2) & 7;
            const int wn_ = (v >> 3) & 3;
            const int ks_ = v >> 5;
            const uint32_t h = pack_bf2(fb[2*i], fb[2*i+1]);
            const uint32_t l = pack_bf2(fb[2*i]   - bf_lo_f(h),
                                        fb[2*i+1] - bf_hi_f(h));
            sBm[bOff(buf,0,ks_,wn_,lane,ni2)] = h;
            sBm[bOff(buf,1,ks_,wn_,lane,ni2)] = l;
        }
    };

    float acc[MI][4][4];
    #pragma unroll
    for (int mi = 0; mi < MI; mi++)
        #pragma unroll
        for (int ni = 0; ni < 4; ni++)
            #pragma unroll
            for (int c = 0; c < 4; c++) acc[mi][ni][c] = 0.f;

    loadA(0); loadB(0);
    storeAB(0);
    __syncthreads();

    for (int it = 0; it < NT; it++) {
        const int cur  = it & 1;
        const bool more = (it + 1 < NT);
        if (more) { loadA((it+1)*BK); loadB((it+1)*BK); }

        #pragma unroll
        for (int ks = 0; ks < 2; ks++) {
            uint4 afv[2][MI];
            #pragma unroll
            for (int pa = 0; pa < 2; pa++)
                #pragma unroll
                for (int mi = 0; mi < MI; mi++)
                    afv[pa][mi] = *reinterpret_cast<const uint4*>(
                        &sm[aOff(cur,pa,ks,wm,lane,mi*4)]);
            uint2 bvv[2][4];
            #pragma unroll
            for (int pb = 0; pb < 2; pb++)
                #pragma unroll
                for (int ni = 0; ni < 4; ni++)
                    bvv[pb][ni] = *reinterpret_cast<const uint2*>(
                        &sBm[bOff(cur,pb,ks,wn,lane,ni*2)]);

            #pragma unroll
            for (int p = 0; p < 3; p++) {
                const int pa = (p == 2) ? 1 : 0;
                const int pb = (p == 1) ? 1 : 0;
                #pragma unroll
                for (int ni = 0; ni < 4; ni++)
                    #pragma unroll
                    for (int mi = 0; mi < MI; mi++)
                        mma_bf16(acc[mi][ni],
                                 reinterpret_cast<const uint32_t*>(&afv[pa][mi]),
                                 bvv[pb][ni].x, bvv[pb][ni].y);
            }
        }

        if (more) {
            storeAB(cur ^ 1);
            __syncthreads();
        }
    }

    // ---- epilogue: direct register -> gmem (float2 per c-pair) ----
    const int b2   = nTile / HW;
    const int pix0 = nTile % HW;
    #pragma unroll
    for (int mi = 0; mi < MI; mi++) {
        const int r0 = mTile + mb + mi*16 + gidl;
        const int r1 = r0 + 8;
        const bool v0 = (r0 < M);
        const bool v1 = (r1 < M);
        const float bv0 = v0 ? bias[r0] : 0.f;
        const float bv1 = v1 ? bias[r1] : 0.f;
        #pragma unroll
        for (int ni = 0; ni < 4; ni++) {
            const int nloc = nb + ni*8 + tidl*2;
            if (v0) {
                float2 o0 = make_float2(acc[mi][ni][0] + bv0, acc[mi][ni][1] + bv0);
                *reinterpret_cast<float2*>(out + ((size_t)b2*M + r0)*HW + pix0 + nloc) = o0;
            }
            if (v1) {
                float2 o1 = make_float2(acc[mi][ni][2] + bv1, acc[mi][ni][3] + bv1);
                *reinterpret_cast<float2*>(out + ((size_t)b2*M + r1)*HW + pix0 + nloc) = o1;
            }
        }
    }
}

// smem byte sizes per BM
static constexpr int smemBytes(int BM){
    const int SAV = BM/8 + 4;
    return (512*SAV + 10240) * 4;
}

// ---------------------------------------------------------------------------
// DCNv2 sampling: col[b, ci*K + k, pix] = mask * bilinear(x[b,ci], ys, xs)
// ---------------------------------------------------------------------------
template<int CIN,int H,int W,int KH,int KW,int STR,int PAD,int HO,int WO>
__global__ void __launch_bounds__(256)
deform_sample_kernel(const float* __restrict__ x, const float* __restrict__ om,
                     float* __restrict__ col)
{
    constexpr int B  = 16;
    constexpr int K  = KH*KW;
    constexpr int HW = HO*WO;

    const int idx = blockIdx.x*blockDim.x + threadIdx.x;
    if (idx >= B*K*HW) return;

    const int ox  = idx % WO;
    int tmp       = idx / WO;
    const int oy  = tmp % HO;  tmp /= HO;
    const int k   = tmp % K;
    const int b   = tmp / K;
    const int ky  = k / KW;
    const int kx  = k % KW;

    const int pix = oy*WO + ox;
    const float offy = om[((size_t)(b*3*K + 2*k    )*HW) + pix];
    const float offx = om[((size_t)(b*3*K + 2*k + 1)*HW) + pix];
    const float mv   = om[((size_t)(b*3*K + 2*K + k)*HW) + pix];
    const float mask = 1.f / (1.f + expf(-mv));

    const float ys = (float)(oy*STR - PAD + ky) + offy;
    const float xs = (float)(ox*STR - PAD + kx) + offx;

    const float y0f = floorf(ys), x0f = floorf(xs);
    const float dy = ys - y0f,    dx = xs - x0f;
    const int y0 = (int)y0f, x0 = (int)x0f;
    const int y1 = y0 + 1,   x1 = x0 + 1;

    const bool vy0 = (y0 >= 0) & (y0 < H);
    const bool vy1 = (y1 >= 0) & (y1 < H);
    const bool vx0 = (x0 >= 0) & (x0 < W);
    const bool vx1 = (x1 >= 0) & (x1 < W);

    const int cy0 = min(max(y0, 0), H-1), cy1 = min(max(y1, 0), H-1);
    const int cx0 = min(max(x0, 0), W-1), cx1 = min(max(x1, 0), W-1);

    const float f00 = (vy0 && vx0) ? (1.f-dy)*(1.f-dx)*mask : 0.f;
    const float f01 = (vy0 && vx1) ? (1.f-dy)*dx*mask       : 0.f;
    const float f10 = (vy1 && vx0) ? dy*(1.f-dx)*mask       : 0.f;
    const float f11 = (vy1 && vx1) ? dy*dx*mask             : 0.f;

    const int i00 = cy0*W + cx0, i01 = cy0*W + cx1;
    const int i10 = cy1*W + cx0, i11 = cy1*W + cx1;

    const float* xb = x + (size_t)b*CIN*H*W;
    float* cp = col + (((size_t)b*CIN*K + k)*HW) + pix;

    #pragma unroll 4
    for (int ci = 0; ci < CIN; ci++) {
        const float* img = xb + (size_t)ci*H*W;
        const float v = f00*img[i00] + f01*img[i01] + f10*img[i10] + f11*img[i11];
        cp[(size_t)ci*K*HW] = v;
    }
}

// ---------------------------------------------------------------------------
// Instance norm: single stats pass (sum+sumsq, float4) + write pass.
// ---------------------------------------------------------------------------
__global__ void __launch_bounds__(256)
instnorm_kernel(const float* __restrict__ in, float* __restrict__ out,
                const float* __restrict__ addsrc, int HW, int relu)
{
    const int bc = blockIdx.x;
    const int HW4 = HW >> 2;
    const float4* p4 = reinterpret_cast<const float4*>(in) + (size_t)bc*HW4;
    float4* q4 = reinterpret_cast<float4*>(out) + (size_t)bc*HW4;
    const float4* a4 = addsrc ?
        reinterpret_cast<const float4*>(addsrc) + (size_t)bc*HW4 : nullptr;

    __shared__ float redS[256];
    __shared__ float redQ[256];
    __shared__ float s_mu, s_rs;
    const int t = threadIdx.x;

    float s = 0.f, q = 0.f;
    for (int i = t; i < HW4; i += 256) {
        const float4 v = p4[i];
        s += v.x + v.y + v.z + v.w;
        q += v.x*v.x + v.y*v.y + v.z*v.z + v.w*v.w;
    }
    redS[t] = s; redQ[t] = q; __syncthreads();
    for (int o = 128; o > 0; o >>= 1) {
        if (t < o) { redS[t] += redS[t+o]; redQ[t] += redQ[t+o]; }
        __syncthreads();
    }
    if (t == 0) {
        const float mu = redS[0] / (float)HW;
        float var = redQ[0] / (float)HW - mu*mu;
        var = fmaxf(var, 0.f);
        s_mu = mu;
        s_rs = rsqrtf(var + 1e-5f);
    }
    __syncthreads();
    const float mu = s_mu;
    const float rs = s_rs;

    for (int i = t; i < HW4; i += 256) {
        float4 v = p4[i];
        v.x = (v.x - mu)*rs; v.y = (v.y - mu)*rs;
        v.z = (v.z - mu)*rs; v.w = (v.w - mu)*rs;
        if (relu) {
            v.x = fmaxf(v.x, 0.f); v.y = fmaxf(v.y, 0.f);
            v.z = fmaxf(v.z, 0.f); v.w = fmaxf(v.w, 0.f);
        }
        if (a4) {
            const float4 a = a4[i];
            v.x += a.x; v.y += a.y; v.z += a.z; v.w += a.w;
        }
        q4[i] = v;
    }
}

// ---------------------------------------------------------------------------
// Launch
// ---------------------------------------------------------------------------
extern "C" void kernel_launch(void* const* d_in, const int* in_sizes, int n_in,
                              void* d_out, int out_size)
{
    const float* x      = (const float*)d_in[0];
    const float* w_off1 = (const float*)d_in[1];
    const float* b_off1 = (const float*)d_in[2];
    const float* w1     = (const float*)d_in[3];
    const float* b1     = (const float*)d_in[4];
    const float* w_off2 = (const float*)d_in[5];
    const float* b_off2 = (const float*)d_in[6];
    const float* w2     = (const float*)d_in[7];
    const float* b2     = (const float*)d_in[8];
    const float* w_off3 = (const float*)d_in[9];
    const float* b_off3 = (const float*)d_in[10];
    const float* w3     = (const float*)d_in[11];
    const float* b3     = (const float*)d_in[12];
    const float* rw0a   = (const float*)d_in[13];
    const float* rb0a   = (const float*)d_in[14];
    const float* rw0b   = (const float*)d_in[15];
    const float* rb0b   = (const float*)d_in[16];
    const float* rw1a   = (const float*)d_in[17];
    const float* rb1a   = (const float*)d_in[18];
    const float* rw1b   = (const float*)d_in[19];
    const float* rb1b   = (const float*)d_in[20];

    float* out = (float*)d_out;
    float* out_h  = out;                                   // [16,256,32,32]
    float* out_s2 = out + 16*256*32*32;                    // [16,128,64,64]
    float* out_s3 = out + 16*256*32*32 + 16*128*64*64;     // [16,256,32,32]

    float *om1,*col1,*t1,*om2,*col2,*t2,*om3,*col3,*t3,*ybuf,*cvb,*hbuf;
    cudaGetSymbolAddress((void**)&om1,  g_om1);
    cudaGetSymbolAddress((void**)&col1, g_col1);
    cudaGetSymbolAddress((void**)&t1,   g_t1);
    cudaGetSymbolAddress((void**)&om2,  g_om2);
    cudaGetSymbolAddress((void**)&col2, g_col2);
    cudaGetSymbolAddress((void**)&t2,   g_t2);
    cudaGetSymbolAddress((void**)&om3,  g_om3);
    cudaGetSymbolAddress((void**)&col3, g_col3);
    cudaGetSymbolAddress((void**)&t3,   g_t3);
    cudaGetSymbolAddress((void**)&ybuf, g_y);
    cudaGetSymbolAddress((void**)&cvb,  g_cv);
    cudaGetSymbolAddress((void**)&hbuf, g_h);

    constexpr int S64  = smemBytes(64);    // 65536
    constexpr int S128 = smemBytes(128);   // 81920

    auto setmax = [](const void* f, int bytes){
        cudaFuncSetAttribute(f, cudaFuncAttributeMaxDynamicSharedMemorySize, bytes);
    };
    setmax((const void*)conv_mma<3,128,128,7,7,1,3,128,128,0,64>,     S64);
    setmax((const void*)conv_mma<147,128,128,1,1,1,0,128,128,0,64>,   S64);
    setmax((const void*)conv_mma<64,128,128,4,4,2,1,64,64,0,64>,      S64);
    setmax((const void*)conv_mma<1024,64,64,1,1,1,0,64,64,0,128>,     S128);
    setmax((const void*)conv_mma<128,64,64,4,4,2,1,32,32,0,64>,       S64);
    setmax((const void*)conv_mma<2048,32,32,1,1,1,0,32,32,0,128>,     S128);
    setmax((const void*)conv_mma<256,32,32,3,3,1,1,32,32,1,128>,      S128);

    // ------------------ Stage 1: 3 -> 64, 7x7, s1 p3, 128x128 ------------------
    {
        conv_mma<3,128,128,7,7,1,3,128,128,0,64>
            <<<dim3(2048, 3), 256, S64>>>(x, w_off1, b_off1, om1, 147);

        const int tot = 16*49*128*128;
        deform_sample_kernel<3,128,128,7,7,1,3,128,128>
            <<<(tot+255)/256, 256>>>(x, om1, col1);

        conv_mma<147,128,128,1,1,1,0,128,128,0,64>
            <<<dim3(2048, 1), 256, S64>>>(col1, w1, b1, t1, 64);

        instnorm_kernel<<<16*64, 256>>>(t1, t1, nullptr, 128*128, 1);
    }

    // ------------------ Stage 2: 64 -> 128, 4x4, s2 p1, -> 64x64 ---------------
    {
        conv_mma<64,128,128,4,4,2,1,64,64,0,64>
            <<<dim3(512, 1), 256, S64>>>(t1, w_off2, b_off2, om2, 48);

        const int tot = 16*16*64*64;
        deform_sample_kernel<64,128,128,4,4,2,1,64,64>
            <<<(tot+255)/256, 256>>>(t1, om2, col2);

        conv_mma<1024,64,64,1,1,1,0,64,64,0,128>
            <<<dim3(512, 1), 256, S128>>>(col2, w2, b2, t2, 128);

        instnorm_kernel<<<16*128, 256>>>(t2, out_s2, nullptr, 64*64, 1);   // skip2
    }

    // ------------------ Stage 3: 128 -> 256, 4x4, s2 p1, -> 32x32 --------------
    {
        conv_mma<128,64,64,4,4,2,1,32,32,0,64>
            <<<dim3(128, 1), 256, S64>>>(out_s2, w_off3, b_off3, om3, 48);

        const int tot = 16*16*32*32;
        deform_sample_kernel<128,64,64,4,4,2,1,32,32>
            <<<(tot+255)/256, 256>>>(out_s2, om3, col3);

        conv_mma<2048,32,32,1,1,1,0,32,32,0,128>
            <<<dim3(128, 2), 256, S128>>>(col3, w3, b3, t3, 256);

        instnorm_kernel<<<16*256, 256>>>(t3, out_s3, nullptr, 32*32, 1);   // skip3
    }

    // ------------------ Residual blocks on [16,256,32,32] ----------------------
    const dim3 cgrid(128, 2);

    // block 0: input = skip3 (reads d_out region)
    conv_mma<256,32,32,3,3,1,1,32,32,1,128><<<cgrid, 256, S128>>>(out_s3, rw0a, rb0a, cvb, 256);
    instnorm_kernel<<<16*256, 256>>>(cvb, ybuf, nullptr, 32*32, 1);
    conv_mma<256,32,32,3,3,1,1,32,32,1,128><<<cgrid, 256, S128>>>(ybuf, rw0b, rb0b, cvb, 256);
    instnorm_kernel<<<16*256, 256>>>(cvb, hbuf, out_s3, 32*32, 0);   // h = skip3 + IN(conv)

    // block 1: input = hbuf
    conv_mma<256,32,32,3,3,1,1,32,32,1,128><<<cgrid, 256, S128>>>(hbuf, rw1a, rb1a, cvb, 256);
    instnorm_kernel<<<16*256, 256>>>(cvb, ybuf, nullptr, 32*32, 1);
    conv_mma<256,32,32,3,3,1,1,32,32,1,128><<<cgrid, 256, S128>>>(ybuf, rw1b, rb1b, cvb, 256);
    instnorm_kernel<<<16*256, 256>>>(cvb, out_h, hbuf, 32*32, 0);    // final h
}

// round 15
// speedup vs baseline: 1.5325x; 1.5315x over previous
#include <cuda_runtime.h>
#include <math.h>
#include <stdint.h>

// ---------------------------------------------------------------------------
// Scratch (__device__ globals)
// ---------------------------------------------------------------------------
__device__ float g_om1 [16*147*128*128];
__device__ float g_col1[16*147*128*128];
__device__ float g_t1  [16*64*128*128];
__device__ float g_om2 [16*48*64*64];
__device__ float g_col2[16*1024*64*64];
__device__ float g_t2  [16*128*64*64];
__device__ float g_om3 [16*48*32*32];
__device__ float g_col3[16*2048*32*32];
__device__ float g_t3  [16*256*32*32];
__device__ float g_y   [16*256*32*32];
__device__ float g_cv  [16*256*32*32];
__device__ float g_h   [16*256*32*32];

// ---------------------------------------------------------------------------
// bf16 pack/split helpers
// ---------------------------------------------------------------------------
__device__ __forceinline__ uint32_t pack_bf2(float e0, float e1){
    uint32_t r;  // low half = e0, high half = e1
    asm("cvt.rn.bf16x2.f32 %0, %2, %1;" : "=r"(r) : "f"(e0), "f"(e1));
    return r;
}
__device__ __forceinline__ float bf_lo_f(uint32_t p){ return __uint_as_float(p << 16); }
__device__ __forceinline__ float bf_hi_f(uint32_t p){ return __uint_as_float(p & 0xffff0000u); }

// mma.sync m16n8k16 row.col f32 += bf16*bf16 (sm_80+ baseline PTX -> HMMA)
__device__ __forceinline__ void mma_bf16(float* c, const uint32_t* a,
                                         uint32_t b0, uint32_t b1){
    asm volatile(
        "mma.sync.aligned.m16n8k16.row.col.f32.bf16.bf16.f32 "
        "{%0,%1,%2,%3}, {%4,%5,%6,%7}, {%8,%9}, {%0,%1,%2,%3};"
        : "+f"(c[0]), "+f"(c[1]), "+f"(c[2]), "+f"(c[3])
        : "r"(a[0]), "r"(a[1]), "r"(a[2]), "r"(a[3]), "r"(b0), "r"(b1));
}

// ---------------------------------------------------------------------------
// Conv-as-GEMM via mma.sync bf16, hi/lo split, 3 passes (hi*hi + hi*lo + lo*hi).
// Tile BM(M) x 128(N), K chunk 32 fp32. 8 warps: 2(m) x 4(n).
// Fragment-native smem layout: A frags read via LDS.128, B via LDS.64,
// conflict-free both sides; frag sets loaded once per ks, reused over passes.
// ---------------------------------------------------------------------------
template<int CIN,int H,int W,int KH,int KW,int STR,int PAD,int HO,int WO,int REFLECT,int BM>
__global__ void __launch_bounds__(256, (BM==64) ? 2 : 1)
conv_mma(const float* __restrict__ in, const float* __restrict__ Wt,
         const float* __restrict__ bias, float* __restrict__ out, int M)
{
    constexpr int Kdim = CIN*KH*KW;
    constexpr int HW   = HO*WO;
    constexpr int BK   = 32;
    constexpr int NT   = (Kdim + BK - 1)/BK;
    constexpr int MI   = BM/32;            // mi count per warp
    constexpr int SAV  = MI*4 + 4;         // A per-lane stride (u32): odd mult of 16B
    constexpr int AR   = BM/16;            // A producer iters
    constexpr int EMASK= 4*MI - 1;
    constexpr int ESH  = (MI==4) ? 4 : 3;  // log2(4*MI)
    constexpr int A_U32= 512*SAV;          // [2buf][2pa][2ks][2wm][32][SAV]

    extern __shared__ __align__(16) uint32_t sm[];
    uint32_t* sBm = sm + A_U32;            // [2buf][2pb][2ks][4wn][32][10]

    const int t    = threadIdx.x;
    const int lane = t & 31;
    const int w8   = t >> 5;
    const int gidl = lane >> 2;
    const int tidl = lane & 3;
    const int g4   = lane >> 3;            // A store bank-shift group
    const int g2   = lane >> 4;            // B store bank-shift group

    const int wid = w8;
    const int wm  = wid & 1;
    const int wn  = wid >> 1;
    const int mb  = wm*(BM/2);
    const int nb  = wn*32;

    const int nTile = blockIdx.x * 128;
    const int mTile = blockIdx.y * BM;

    auto aOff = [&](int buf,int pa,int ks,int wmi,int ln,int e)->int{
        return ((((buf*2+pa)*2+ks)*2+wmi)*32 + ln)*SAV + e;
    };
    auto bOff = [&](int buf,int pb,int ks,int wni,int ln,int e)->int{
        return ((((buf*2+pb)*2+ks)*4+wni)*32 + ln)*10 + e;
    };

    auto gatherB = [&](int n, int k)->float{
        if (k >= Kdim) return 0.f;
        const int b   = n / HW;
        const int rem = n % HW;
        const int oy  = rem / WO;
        const int ox  = rem % WO;
        const int ci  = k / (KH*KW);
        const int r   = k % (KH*KW);
        const int ky  = r / KW;
        const int kx  = r % KW;
        int iy = oy*STR - PAD + ky;
        int ix = ox*STR - PAD + kx;
        const float* inb = in + (size_t)b*CIN*H*W;
        if (REFLECT) {
            iy = iy < 0 ? -iy : (iy >= H ? 2*H-2-iy : iy);
            ix = ix < 0 ? -ix : (ix >= W ? 2*W-2-ix : ix);
            return inb[((size_t)ci*H + iy)*W + ix];
        }
        if (iy >= 0 && iy < H && ix >= 0 && ix < W)
            return inb[((size_t)ci*H + iy)*W + ix];
        return 0.f;
    };

    float fa[2*AR], fb[16];

    auto loadA = [&](int k0){
        #pragma unroll
        for (int i = 0; i < AR; i++) {
            const int v   = i*8 + w8;
            const int elt = (v + g4) & EMASK;
            const int wm_ = (v >> ESH) & 1;
            const int mi_ = elt >> 2;
            const int j   = elt & 3;
            const int m   = wm_*(BM/2) + mi_*16 + (j & 1)*8 + gidl;
            const int kp  = (v >> (ESH+1))*8 + (j >> 1)*4 + tidl;
            const int gm  = mTile + m;
            const int k   = k0 + kp*2;
            const bool mv = (gm < M);
            const float* row = Wt + (size_t)gm * (size_t)Kdim;
            fa[2*i]   = (mv && k     < Kdim) ? row[k]   : 0.f;
            fa[2*i+1] = (mv && k + 1 < Kdim) ? row[k+1] : 0.f;
        }
    };
    auto loadB = [&](int k0){
        #pragma unroll
        for (int i = 0; i < 8; i++) {
            const int v   = i*8 + w8;
            const int ni2 = ((v & 7) + g2) & 7;
            const int wn_ = (v >> 3) & 3;
            const int ks_ = v >> 5;
            const int n   = nTile + wn_*32 + (ni2 >> 1)*8 + gidl;
            const int kp  = ks_*8 + (ni2 & 1)*4 + tidl;
            const int k   = k0 + kp*2;
            fb[2*i]   = gatherB(n, k);
            fb[2*i+1] = gatherB(n, k+1);
        }
    };
    auto storeAB = [&](int buf){
        #pragma unroll
        for (int i = 0; i < AR; i++) {
            const int v   = i*8 + w8;
            const int elt = (v + g4) & EMASK;
            const int wm_ = (v >> ESH) & 1;
            const int ks_ = v >> (ESH+1);
            const uint32_t h = pack_bf2(fa[2*i], fa[2*i+1]);
            const uint32_t l = pack_bf2(fa[2*i]   - bf_lo_f(h),
                                        fa[2*i+1] - bf_hi_f(h));
            sm[aOff(buf,0,ks_,wm_,lane,elt)] = h;
            sm[aOff(buf,1,ks_,wm_,lane,elt)] = l;
        }
        #pragma unroll
        for (int i = 0; i < 8; i++) {
            const int v   = i*8 + w8;
            const int ni2 = ((v & 7) + g2) & 7;
            const int wn_ = (v >> 3) & 3;
            const int ks_ = v >> 5;
            const uint32_t h = pack_bf2(fb[2*i], fb[2*i+1]);
            const uint32_t l = pack_bf2(fb[2*i]   - bf_lo_f(h),
                                        fb[2*i+1] - bf_hi_f(h));
            sBm[bOff(buf,0,ks_,wn_,lane,ni2)] = h;
            sBm[bOff(buf,1,ks_,wn_,lane,ni2)] = l;
        }
    };

    float acc[MI][4][4];
    #pragma unroll
    for (int mi = 0; mi < MI; mi++)
        #pragma unroll
        for (int ni = 0; ni < 4; ni++)
            #pragma unroll
            for (int c = 0; c < 4; c++) acc[mi][ni][c] = 0.f;

    loadA(0); loadB(0);
    storeAB(0);
    __syncthreads();

    for (int it = 0; it < NT; it++) {
        const int cur  = it & 1;
        const bool more = (it + 1 < NT);
        if (more) { loadA((it+1)*BK); loadB((it+1)*BK); }

        #pragma unroll
        for (int ks = 0; ks < 2; ks++) {
            uint4 afv[2][MI];
            #pragma unroll
            for (int pa = 0; pa < 2; pa++)
                #pragma unroll
                for (int mi = 0; mi < MI; mi++)
                    afv[pa][mi] = *reinterpret_cast<const uint4*>(
                        &sm[aOff(cur,pa,ks,wm,lane,mi*4)]);
            uint2 bvv[2][4];
            #pragma unroll
            for (int pb = 0; pb < 2; pb++)
                #pragma unroll
                for (int ni = 0; ni < 4; ni++)
                    bvv[pb][ni] = *reinterpret_cast<const uint2*>(
                        &sBm[bOff(cur,pb,ks,wn,lane,ni*2)]);

            #pragma unroll
            for (int p = 0; p < 3; p++) {
                const int pa = (p == 2) ? 1 : 0;
                const int pb = (p == 1) ? 1 : 0;
                #pragma unroll
                for (int ni = 0; ni < 4; ni++)
                    #pragma unroll
                    for (int mi = 0; mi < MI; mi++)
                        mma_bf16(acc[mi][ni],
                                 reinterpret_cast<const uint32_t*>(&afv[pa][mi]),
                                 bvv[pb][ni].x, bvv[pb][ni].y);
            }
        }

        if (more) {
            storeAB(cur ^ 1);
            __syncthreads();
        }
    }

    // ---- epilogue: direct register -> gmem (float2 per c-pair) ----
    const int b2   = nTile / HW;
    const int pix0 = nTile % HW;
    #pragma unroll
    for (int mi = 0; mi < MI; mi++) {
        const int r0 = mTile + mb + mi*16 + gidl;
        const int r1 = r0 + 8;
        const bool v0 = (r0 < M);
        const bool v1 = (r1 < M);
        const float bv0 = v0 ? bias[r0] : 0.f;
        const float bv1 = v1 ? bias[r1] : 0.f;
        #pragma unroll
        for (int ni = 0; ni < 4; ni++) {
            const int nloc = nb + ni*8 + tidl*2;
            if (v0) {
                float2 o0 = make_float2(acc[mi][ni][0] + bv0, acc[mi][ni][1] + bv0);
                *reinterpret_cast<float2*>(out + ((size_t)b2*M + r0)*HW + pix0 + nloc) = o0;
            }
            if (v1) {
                float2 o1 = make_float2(acc[mi][ni][2] + bv1, acc[mi][ni][3] + bv1);
                *reinterpret_cast<float2*>(out + ((size_t)b2*M + r1)*HW + pix0 + nloc) = o1;
            }
        }
    }
}

// smem byte sizes per BM
static constexpr int smemBytes(int BM){
    const int SAV = BM/8 + 4;
    return (512*SAV + 10240) * 4;
}

// ---------------------------------------------------------------------------
// DCNv2 sampling: col[b, ci*K + k, pix] = mask * bilinear(x[b,ci], ys, xs)
// ---------------------------------------------------------------------------
template<int CIN,int H,int W,int KH,int KW,int STR,int PAD,int HO,int WO>
__global__ void __launch_bounds__(256)
deform_sample_kernel(const float* __restrict__ x, const float* __restrict__ om,
                     float* __restrict__ col)
{
    constexpr int B  = 16;
    constexpr int K  = KH*KW;
    constexpr int HW = HO*WO;

    const int idx = blockIdx.x*blockDim.x + threadIdx.x;
    if (idx >= B*K*HW) return;

    const int ox  = idx % WO;
    int tmp       = idx / WO;
    const int oy  = tmp % HO;  tmp /= HO;
    const int k   = tmp % K;
    const int b   = tmp / K;
    const int ky  = k / KW;
    const int kx  = k % KW;

    const int pix = oy*WO + ox;
    const float offy = om[((size_t)(b*3*K + 2*k    )*HW) + pix];
    const float offx = om[((size_t)(b*3*K + 2*k + 1)*HW) + pix];
    const float mv   = om[((size_t)(b*3*K + 2*K + k)*HW) + pix];
    const float mask = 1.f / (1.f + expf(-mv));

    const float ys = (float)(oy*STR - PAD + ky) + offy;
    const float xs = (float)(ox*STR - PAD + kx) + offx;

    const float y0f = floorf(ys), x0f = floorf(xs);
    const float dy = ys - y0f,    dx = xs - x0f;
    const int y0 = (int)y0f, x0 = (int)x0f;
    const int y1 = y0 + 1,   x1 = x0 + 1;

    const bool vy0 = (y0 >= 0) & (y0 < H);
    const bool vy1 = (y1 >= 0) & (y1 < H);
    const bool vx0 = (x0 >= 0) & (x0 < W);
    const bool vx1 = (x1 >= 0) & (x1 < W);

    const int cy0 = min(max(y0, 0), H-1), cy1 = min(max(y1, 0), H-1);
    const int cx0 = min(max(x0, 0), W-1), cx1 = min(max(x1, 0), W-1);

    const float f00 = (vy0 && vx0) ? (1.f-dy)*(1.f-dx)*mask : 0.f;
    const float f01 = (vy0 && vx1) ? (1.f-dy)*dx*mask       : 0.f;
    const float f10 = (vy1 && vx0) ? dy*(1.f-dx)*mask       : 0.f;
    const float f11 = (vy1 && vx1) ? dy*dx*mask             : 0.f;

    const int i00 = cy0*W + cx0, i01 = cy0*W + cx1;
    const int i10 = cy1*W + cx0, i11 = cy1*W + cx1;

    const float* xb = x + (size_t)b*CIN*H*W;
    float* cp = col + (((size_t)b*CIN*K + k)*HW) + pix;

    #pragma unroll 4
    for (int ci = 0; ci < CIN; ci++) {
        const float* img = xb + (size_t)ci*H*W;
        const float v = f00*img[i00] + f01*img[i01] + f10*img[i10] + f11*img[i11];
        cp[(size_t)ci*K*HW] = v;
    }
}

// ---------------------------------------------------------------------------
// Instance norm: single stats pass (sum+sumsq, float4) + write pass.
// ---------------------------------------------------------------------------
__global__ void __launch_bounds__(256)
instnorm_kernel(const float* __restrict__ in, float* __restrict__ out,
                const float* __restrict__ addsrc, int HW, int relu)
{
    const int bc = blockIdx.x;
    const int HW4 = HW >> 2;
    const float4* p4 = reinterpret_cast<const float4*>(in) + (size_t)bc*HW4;
    float4* q4 = reinterpret_cast<float4*>(out) + (size_t)bc*HW4;
    const float4* a4 = addsrc ?
        reinterpret_cast<const float4*>(addsrc) + (size_t)bc*HW4 : nullptr;

    __shared__ float redS[256];
    __shared__ float redQ[256];
    __shared__ float s_mu, s_rs;
    const int t = threadIdx.x;

    float s = 0.f, q = 0.f;
    for (int i = t; i < HW4; i += 256) {
        const float4 v = p4[i];
        s += v.x + v.y + v.z + v.w;
        q += v.x*v.x + v.y*v.y + v.z*v.z + v.w*v.w;
    }
    redS[t] = s; redQ[t] = q; __syncthreads();
    for (int o = 128; o > 0; o >>= 1) {
        if (t < o) { redS[t] += redS[t+o]; redQ[t] += redQ[t+o]; }
        __syncthreads();
    }
    if (t == 0) {
        const float mu = redS[0] / (float)HW;
        float var = redQ[0] / (float)HW - mu*mu;
        var = fmaxf(var, 0.f);
        s_mu = mu;
        s_rs = rsqrtf(var + 1e-5f);
    }
    __syncthreads();
    const float mu = s_mu;
    const float rs = s_rs;

    for (int i = t; i < HW4; i += 256) {
        float4 v = p4[i];
        v.x = (v.x - mu)*rs; v.y = (v.y - mu)*rs;
        v.z = (v.z - mu)*rs; v.w = (v.w - mu)*rs;
        if (relu) {
            v.x = fmaxf(v.x, 0.f); v.y = fmaxf(v.y, 0.f);
            v.z = fmaxf(v.z, 0.f); v.w = fmaxf(v.w, 0.f);
        }
        if (a4) {
            const float4 a = a4[i];
            v.x += a.x; v.y += a.y; v.z += a.z; v.w += a.w;
        }
        q4[i] = v;
    }
}

// ---------------------------------------------------------------------------
// Launch
// ---------------------------------------------------------------------------
extern "C" void kernel_launch(void* const* d_in, const int* in_sizes, int n_in,
                              void* d_out, int out_size)
{
    const float* x      = (const float*)d_in[0];
    const float* w_off1 = (const float*)d_in[1];
    const float* b_off1 = (const float*)d_in[2];
    const float* w1     = (const float*)d_in[3];
    const float* b1     = (const float*)d_in[4];
    const float* w_off2 = (const float*)d_in[5];
    const float* b_off2 = (const float*)d_in[6];
    const float* w2     = (const float*)d_in[7];
    const float* b2     = (const float*)d_in[8];
    const float* w_off3 = (const float*)d_in[9];
    const float* b_off3 = (const float*)d_in[10];
    const float* w3     = (const float*)d_in[11];
    const float* b3     = (const float*)d_in[12];
    const float* rw0a   = (const float*)d_in[13];
    const float* rb0a   = (const float*)d_in[14];
    const float* rw0b   = (const float*)d_in[15];
    const float* rb0b   = (const float*)d_in[16];
    const float* rw1a   = (const float*)d_in[17];
    const float* rb1a   = (const float*)d_in[18];
    const float* rw1b   = (const float*)d_in[19];
    const float* rb1b   = (const float*)d_in[20];

    float* out = (float*)d_out;
    float* out_h  = out;                                   // [16,256,32,32]
    float* out_s2 = out + 16*256*32*32;                    // [16,128,64,64]
    float* out_s3 = out + 16*256*32*32 + 16*128*64*64;     // [16,256,32,32]

    float *om1,*col1,*t1,*om2,*col2,*t2,*om3,*col3,*t3,*ybuf,*cvb,*hbuf;
    cudaGetSymbolAddress((void**)&om1,  g_om1);
    cudaGetSymbolAddress((void**)&col1, g_col1);
    cudaGetSymbolAddress((void**)&t1,   g_t1);
    cudaGetSymbolAddress((void**)&om2,  g_om2);
    cudaGetSymbolAddress((void**)&col2, g_col2);
    cudaGetSymbolAddress((void**)&t2,   g_t2);
    cudaGetSymbolAddress((void**)&om3,  g_om3);
    cudaGetSymbolAddress((void**)&col3, g_col3);
    cudaGetSymbolAddress((void**)&t3,   g_t3);
    cudaGetSymbolAddress((void**)&ybuf, g_y);
    cudaGetSymbolAddress((void**)&cvb,  g_cv);
    cudaGetSymbolAddress((void**)&hbuf, g_h);

    constexpr int S64  = smemBytes(64);    // 65536
    constexpr int S128 = smemBytes(128);   // 81920

    auto setmax = [](const void* f, int bytes){
        cudaFuncSetAttribute(f, cudaFuncAttributeMaxDynamicSharedMemorySize, bytes);
    };
    setmax((const void*)conv_mma<3,128,128,7,7,1,3,128,128,0,64>,     S64);
    setmax((const void*)conv_mma<147,128,128,1,1,1,0,128,128,0,64>,   S64);
    setmax((const void*)conv_mma<64,128,128,4,4,2,1,64,64,0,64>,      S64);
    setmax((const void*)conv_mma<1024,64,64,1,1,1,0,64,64,0,128>,     S128);
    setmax((const void*)conv_mma<128,64,64,4,4,2,1,32,32,0,64>,       S64);
    setmax((const void*)conv_mma<2048,32,32,1,1,1,0,32,32,0,128>,     S128);
    setmax((const void*)conv_mma<256,32,32,3,3,1,1,32,32,1,128>,      S128);

    // ------------------ Stage 1: 3 -> 64, 7x7, s1 p3, 128x128 ------------------
    {
        conv_mma<3,128,128,7,7,1,3,128,128,0,64>
            <<<dim3(2048, 3), 256, S64>>>(x, w_off1, b_off1, om1, 147);

        const int tot = 16*49*128*128;
        deform_sample_kernel<3,128,128,7,7,1,3,128,128>
            <<<(tot+255)/256, 256>>>(x, om1, col1);

        conv_mma<147,128,128,1,1,1,0,128,128,0,64>
            <<<dim3(2048, 1), 256, S64>>>(col1, w1, b1, t1, 64);

        instnorm_kernel<<<16*64, 256>>>(t1, t1, nullptr, 128*128, 1);
    }

    // ------------------ Stage 2: 64 -> 128, 4x4, s2 p1, -> 64x64 ---------------
    {
        conv_mma<64,128,128,4,4,2,1,64,64,0,64>
            <<<dim3(512, 1), 256, S64>>>(t1, w_off2, b_off2, om2, 48);

        const int tot = 16*16*64*64;
        deform_sample_kernel<64,128,128,4,4,2,1,64,64>
            <<<(tot+255)/256, 256>>>(t1, om2, col2);

        conv_mma<1024,64,64,1,1,1,0,64,64,0,128>
            <<<dim3(512, 1), 256, S128>>>(col2, w2, b2, t2, 128);

        instnorm_kernel<<<16*128, 256>>>(t2, out_s2, nullptr, 64*64, 1);   // skip2
    }

    // ------------------ Stage 3: 128 -> 256, 4x4, s2 p1, -> 32x32 --------------
    {
        conv_mma<128,64,64,4,4,2,1,32,32,0,64>
            <<<dim3(128, 1), 256, S64>>>(out_s2, w_off3, b_off3, om3, 48);

        const int tot = 16*16*32*32;
        deform_sample_kernel<128,64,64,4,4,2,1,32,32>
            <<<(tot+255)/256, 256>>>(out_s2, om3, col3);

        conv_mma<2048,32,32,1,1,1,0,32,32,0,128>
            <<<dim3(128, 2), 256, S128>>>(col3, w3, b3, t3, 256);

        instnorm_kernel<<<16*256, 256>>>(t3, out_s3, nullptr, 32*32, 1);   // skip3
    }

    // ------------------ Residual blocks on [16,256,32,32] ----------------------
    const dim3 cgrid(128, 2);

    // block 0: input = skip3 (reads d_out region)
    conv_mma<256,32,32,3,3,1,1,32,32,1,128><<<cgrid, 256, S128>>>(out_s3, rw0a, rb0a, cvb, 256);
    instnorm_kernel<<<16*256, 256>>>(cvb, ybuf, nullptr, 32*32, 1);
    conv_mma<256,32,32,3,3,1,1,32,32,1,128><<<cgrid, 256, S128>>>(ybuf, rw0b, rb0b, cvb, 256);
    instnorm_kernel<<<16*256, 256>>>(cvb, hbuf, out_s3, 32*32, 0);   // h = skip3 + IN(conv)

    // block 1: input = hbuf
    conv_mma<256,32,32,3,3,1,1,32,32,1,128><<<cgrid, 256, S128>>>(hbuf, rw1a, rb1a, cvb, 256);
    instnorm_kernel<<<16*256, 256>>>(cvb, ybuf, nullptr, 32*32, 1);
    conv_mma<256,32,32,3,3,1,1,32,32,1,128><<<cgrid, 256, S128>>>(ybuf, rw1b, rb1b, cvb, 256);
    instnorm_kernel<<<16*256, 256>>>(cvb, out_h, hbuf, 32*32, 0);    // final h
}

// round 16
// speedup vs baseline: 1.5725x; 1.0261x over previous
#include <cuda_runtime.h>
#include <math.h>
#include <stdint.h>

// ---------------------------------------------------------------------------
// Scratch (__device__ globals)
// ---------------------------------------------------------------------------
__device__ float g_om1 [16*147*128*128];
__device__ float g_col1[16*147*128*128];
__device__ float g_t1  [16*64*128*128];
__device__ float g_om2 [16*48*64*64];
__device__ float g_col2[16*1024*64*64];
__device__ float g_t2  [16*128*64*64];
__device__ float g_om3 [16*48*32*32];
__device__ float g_col3[16*2048*32*32];
__device__ float g_t3  [16*256*32*32];
__device__ float g_y   [16*256*32*32];
__device__ float g_cv  [16*256*32*32];
__device__ float g_h   [16*256*32*32];

// ---------------------------------------------------------------------------
// bf16 pack/split helpers
// ---------------------------------------------------------------------------
__device__ __forceinline__ uint32_t pack_bf2(float e0, float e1){
    uint32_t r;  // low half = e0, high half = e1
    asm("cvt.rn.bf16x2.f32 %0, %2, %1;" : "=r"(r) : "f"(e0), "f"(e1));
    return r;
}
__device__ __forceinline__ float bf_lo_f(uint32_t p){ return __uint_as_float(p << 16); }
__device__ __forceinline__ float bf_hi_f(uint32_t p){ return __uint_as_float(p & 0xffff0000u); }

// mma.sync m16n8k16 row.col f32 += bf16*bf16 (sm_80+ baseline PTX -> HMMA)
__device__ __forceinline__ void mma_bf16(float* c, const uint32_t* a,
                                         uint32_t b0, uint32_t b1){
    asm volatile(
        "mma.sync.aligned.m16n8k16.row.col.f32.bf16.bf16.f32 "
        "{%0,%1,%2,%3}, {%4,%5,%6,%7}, {%8,%9}, {%0,%1,%2,%3};"
        : "+f"(c[0]), "+f"(c[1]), "+f"(c[2]), "+f"(c[3])
        : "r"(a[0]), "r"(a[1]), "r"(a[2]), "r"(a[3]), "r"(b0), "r"(b1));
}

// ---------------------------------------------------------------------------
// Conv-as-GEMM via mma.sync bf16, hi/lo split, 3 passes (hi*hi + hi*lo + lo*hi).
// Tile BM(M) x 128(N), K chunk 32 fp32. 8 warps: 2(m) x 4(n).
// Fragment-native smem layout; frag sets loaded once per ks, reused over passes.
// REFLECT=1: per-block smem table of reflect-resolved neighbor offsets
//            (pixel x tap) makes the B-gather ~7 ops instead of ~16.
// ---------------------------------------------------------------------------
template<int CIN,int H,int W,int KH,int KW,int STR,int PAD,int HO,int WO,int REFLECT,int BM>
__global__ void __launch_bounds__(256, (BM==64) ? 2 : 1)
conv_mma(const float* __restrict__ in, const float* __restrict__ Wt,
         const float* __restrict__ bias, float* __restrict__ out, int M)
{
    constexpr int KK   = KH*KW;
    constexpr int Kdim = CIN*KK;
    constexpr int HW   = HO*WO;
    constexpr int BK   = 32;
    constexpr int NT   = (Kdim + BK - 1)/BK;
    constexpr int MI   = BM/32;            // mi count per warp
    constexpr int SAV  = MI*4 + 4;         // A per-lane stride (u32): odd mult of 16B
    constexpr int AR   = BM/16;            // A producer iters
    constexpr int EMASK= 4*MI - 1;
    constexpr int ESH  = (MI==4) ? 4 : 3;  // log2(4*MI)
    constexpr int A_U32= 512*SAV;          // [2buf][2pa][2ks][2wm][32][SAV]
    constexpr int B_U32= 10240;            // [2buf][2pb][2ks][4wn][32][10]

    extern __shared__ __align__(16) uint32_t sm[];
    uint32_t* sBm = sm + A_U32;
    int* tab = reinterpret_cast<int*>(sm + A_U32 + B_U32);  // [128][KK] (REFLECT)

    const int t    = threadIdx.x;
    const int lane = t & 31;
    const int w8   = t >> 5;
    const int gidl = lane >> 2;
    const int tidl = lane & 3;
    const int g4   = lane >> 3;            // A store bank-shift group
    const int g2   = lane >> 4;            // B store bank-shift group

    const int wid = w8;
    const int wm  = wid & 1;
    const int wn  = wid >> 1;
    const int mb  = wm*(BM/2);
    const int nb  = wn*32;

    const int nTile = blockIdx.x * 128;
    const int mTile = blockIdx.y * BM;

    // REFLECT invariants: one image per tile (128 | HW), base pointer
    const int bTile = nTile / HW;
    const float* inbT = in + (size_t)bTile*CIN*H*W;

    auto aOff = [&](int buf,int pa,int ks,int wmi,int ln,int e)->int{
        return ((((buf*2+pa)*2+ks)*2+wmi)*32 + ln)*SAV + e;
    };
    auto bOff = [&](int buf,int pb,int ks,int wni,int ln,int e)->int{
        return ((((buf*2+pb)*2+ks)*4+wni)*32 + ln)*10 + e;
    };

    // ---- REFLECT: fill pixel x tap offset table (once per block) ----
    if (REFLECT) {
        const int pix0T = nTile % HW;
        for (int e = t; e < 128*KK; e += 256) {
            const int pl  = e / KK;
            const int tap = e % KK;
            const int pix = pix0T + pl;
            const int oy  = pix / WO, ox = pix % WO;
            int iy = oy*STR - PAD + tap/KW;
            int ix = ox*STR - PAD + tap%KW;
            iy = iy < 0 ? -iy : (iy >= H ? 2*H-2-iy : iy);
            ix = ix < 0 ? -ix : (ix >= W ? 2*W-2-ix : ix);
            tab[e] = iy*W + ix;
        }
        __syncthreads();
    }

    auto gatherB = [&](int n, int nloc, int k)->float{
        if (k >= Kdim) return 0.f;
        if (REFLECT) {
            const unsigned uk = (unsigned)k;
            const unsigned ci = uk / (unsigned)KK;
            const unsigned tap = uk - ci*(unsigned)KK;
            return inbT[(size_t)ci*(H*W) + tab[nloc*KK + tap]];
        }
        const int b   = n / HW;
        const int rem = n % HW;
        const int oy  = rem / WO;
        const int ox  = rem % WO;
        const int ci  = k / KK;
        const int r   = k % KK;
        const int ky  = r / KW;
        const int kx  = r % KW;
        const int iy  = oy*STR - PAD + ky;
        const int ix  = ox*STR - PAD + kx;
        const float* inb = in + (size_t)b*CIN*H*W;
        if (iy >= 0 && iy < H && ix >= 0 && ix < W)
            return inb[((size_t)ci*H + iy)*W + ix];
        return 0.f;
    };

    float fa[2*AR], fb[16];

    auto loadA = [&](int k0){
        #pragma unroll
        for (int i = 0; i < AR; i++) {
            const int v   = i*8 + w8;
            const int elt = (v + g4) & EMASK;
            const int wm_ = (v >> ESH) & 1;
            const int mi_ = elt >> 2;
            const int j   = elt & 3;
            const int m   = wm_*(BM/2) + mi_*16 + (j & 1)*8 + gidl;
            const int kp  = (v >> (ESH+1))*8 + (j >> 1)*4 + tidl;
            const int gm  = mTile + m;
            const int k   = k0 + kp*2;
            const bool mv = (gm < M);
            const float* row = Wt + (size_t)gm * (size_t)Kdim;
            fa[2*i]   = (mv && k     < Kdim) ? row[k]   : 0.f;
            fa[2*i+1] = (mv && k + 1 < Kdim) ? row[k+1] : 0.f;
        }
    };
    auto loadB = [&](int k0){
        #pragma unroll
        for (int i = 0; i < 8; i++) {
            const int v    = i*8 + w8;
            const int ni2  = ((v & 7) + g2) & 7;
            const int wn_  = (v >> 3) & 3;
            const int ks_  = v >> 5;
            const int nloc = wn_*32 + (ni2 >> 1)*8 + gidl;
            const int n    = nTile + nloc;
            const int kp   = ks_*8 + (ni2 & 1)*4 + tidl;
            const int k    = k0 + kp*2;
            fb[2*i]   = gatherB(n, nloc, k);
            fb[2*i+1] = gatherB(n, nloc, k+1);
        }
    };
    auto storeAB = [&](int buf){
        #pragma unroll
        for (int i = 0; i < AR; i++) {
            const int v   = i*8 + w8;
            const int elt = (v + g4) & EMASK;
            const int wm_ = (v >> ESH) & 1;
            const int ks_ = v >> (ESH+1);
            const uint32_t h = pack_bf2(fa[2*i], fa[2*i+1]);
            const uint32_t l = pack_bf2(fa[2*i]   - bf_lo_f(h),
                                        fa[2*i+1] - bf_hi_f(h));
            sm[aOff(buf,0,ks_,wm_,lane,elt)] = h;
            sm[aOff(buf,1,ks_,wm_,lane,elt)] = l;
        }
        #pragma unroll
        for (int i = 0; i < 8; i++) {
            const int v   = i*8 + w8;
            const int ni2 = ((v & 7) + g2) & 7;
            const int wn_ = (v >> 3) & 3;
            const int ks_ = v >> 5;
            const uint32_t h = pack_bf2(fb[2*i], fb[2*i+1]);
            const uint32_t l = pack_bf2(fb[2*i]   - bf_lo_f(h),
                                        fb[2*i+1] - bf_hi_f(h));
            sBm[bOff(buf,0,ks_,wn_,lane,ni2)] = h;
            sBm[bOff(buf,1,ks_,wn_,lane,ni2)] = l;
        }
    };

    float acc[MI][4][4];
    #pragma unroll
    for (int mi = 0; mi < MI; mi++)
        #pragma unroll
        for (int ni = 0; ni < 4; ni++)
            #pragma unroll
            for (int c = 0; c < 4; c++) acc[mi][ni][c] = 0.f;

    loadA(0); loadB(0);
    storeAB(0);
    __syncthreads();

    for (int it = 0; it < NT; it++) {
        const int cur  = it & 1;
        const bool more = (it + 1 < NT);
        if (more) { loadA((it+1)*BK); loadB((it+1)*BK); }

        #pragma unroll
        for (int ks = 0; ks < 2; ks++) {
            uint4 afv[2][MI];
            #pragma unroll
            for (int pa = 0; pa < 2; pa++)
                #pragma unroll
                for (int mi = 0; mi < MI; mi++)
                    afv[pa][mi] = *reinterpret_cast<const uint4*>(
                        &sm[aOff(cur,pa,ks,wm,lane,mi*4)]);
            uint2 bvv[2][4];
            #pragma unroll
            for (int pb = 0; pb < 2; pb++)
                #pragma unroll
                for (int ni = 0; ni < 4; ni++)
                    bvv[pb][ni] = *reinterpret_cast<const uint2*>(
                        &sBm[bOff(cur,pb,ks,wn,lane,ni*2)]);

            #pragma unroll
            for (int p = 0; p < 3; p++) {
                const int pa = (p == 2) ? 1 : 0;
                const int pb = (p == 1) ? 1 : 0;
                #pragma unroll
                for (int ni = 0; ni < 4; ni++)
                    #pragma unroll
                    for (int mi = 0; mi < MI; mi++)
                        mma_bf16(acc[mi][ni],
                                 reinterpret_cast<const uint32_t*>(&afv[pa][mi]),
                                 bvv[pb][ni].x, bvv[pb][ni].y);
            }
        }

        if (more) {
            storeAB(cur ^ 1);
            __syncthreads();
        }
    }

    // ---- epilogue: direct register -> gmem (float2 per c-pair) ----
    const int b2   = nTile / HW;
    const int pix0 = nTile % HW;
    #pragma unroll
    for (int mi = 0; mi < MI; mi++) {
        const int r0 = mTile + mb + mi*16 + gidl;
        const int r1 = r0 + 8;
        const bool v0 = (r0 < M);
        const bool v1 = (r1 < M);
        const float bv0 = v0 ? bias[r0] : 0.f;
        const float bv1 = v1 ? bias[r1] : 0.f;
        #pragma unroll
        for (int ni = 0; ni < 4; ni++) {
            const int nloc = nb + ni*8 + tidl*2;
            if (v0) {
                float2 o0 = make_float2(acc[mi][ni][0] + bv0, acc[mi][ni][1] + bv0);
                *reinterpret_cast<float2*>(out + ((size_t)b2*M + r0)*HW + pix0 + nloc) = o0;
            }
            if (v1) {
                float2 o1 = make_float2(acc[mi][ni][2] + bv1, acc[mi][ni][3] + bv1);
                *reinterpret_cast<float2*>(out + ((size_t)b2*M + r1)*HW + pix0 + nloc) = o1;
            }
        }
    }
}

// smem byte sizes
static constexpr int smemBytes(int BM, int reflect_kk){
    const int SAV = BM/8 + 4;
    return (512*SAV + 10240) * 4 + 128*reflect_kk*4;
}

// ---------------------------------------------------------------------------
// DCNv2 sampling: col[b, ci*K + k, pix] = mask * bilinear(x[b,ci], ys, xs)
// ---------------------------------------------------------------------------
template<int CIN,int H,int W,int KH,int KW,int STR,int PAD,int HO,int WO>
__global__ void __launch_bounds__(256)
deform_sample_kernel(const float* __restrict__ x, const float* __restrict__ om,
                     float* __restrict__ col)
{
    constexpr int B  = 16;
    constexpr int K  = KH*KW;
    constexpr int HW = HO*WO;

    const int idx = blockIdx.x*blockDim.x + threadIdx.x;
    if (idx >= B*K*HW) return;

    const int ox  = idx % WO;
    int tmp       = idx / WO;
    const int oy  = tmp % HO;  tmp /= HO;
    const int k   = tmp % K;
    const int b   = tmp / K;
    const int ky  = k / KW;
    const int kx  = k % KW;

    const int pix = oy*WO + ox;
    const float offy = om[((size_t)(b*3*K + 2*k    )*HW) + pix];
    const float offx = om[((size_t)(b*3*K + 2*k + 1)*HW) + pix];
    const float mv   = om[((size_t)(b*3*K + 2*K + k)*HW) + pix];
    const float mask = 1.f / (1.f + expf(-mv));

    const float ys = (float)(oy*STR - PAD + ky) + offy;
    const float xs = (float)(ox*STR - PAD + kx) + offx;

    const float y0f = floorf(ys), x0f = floorf(xs);
    const float dy = ys - y0f,    dx = xs - x0f;
    const int y0 = (int)y0f, x0 = (int)x0f;
    const int y1 = y0 + 1,   x1 = x0 + 1;

    const bool vy0 = (y0 >= 0) & (y0 < H);
    const bool vy1 = (y1 >= 0) & (y1 < H);
    const bool vx0 = (x0 >= 0) & (x0 < W);
    const bool vx1 = (x1 >= 0) & (x1 < W);

    const int cy0 = min(max(y0, 0), H-1), cy1 = min(max(y1, 0), H-1);
    const int cx0 = min(max(x0, 0), W-1), cx1 = min(max(x1, 0), W-1);

    const float f00 = (vy0 && vx0) ? (1.f-dy)*(1.f-dx)*mask : 0.f;
    const float f01 = (vy0 && vx1) ? (1.f-dy)*dx*mask       : 0.f;
    const float f10 = (vy1 && vx0) ? dy*(1.f-dx)*mask       : 0.f;
    const float f11 = (vy1 && vx1) ? dy*dx*mask             : 0.f;

    const int i00 = cy0*W + cx0, i01 = cy0*W + cx1;
    const int i10 = cy1*W + cx0, i11 = cy1*W + cx1;

    const float* xb = x + (size_t)b*CIN*H*W;
    float* cp = col + (((size_t)b*CIN*K + k)*HW) + pix;

    #pragma unroll 4
    for (int ci = 0; ci < CIN; ci++) {
        const float* img = xb + (size_t)ci*H*W;
        const float v = f00*img[i00] + f01*img[i01] + f10*img[i10] + f11*img[i11];
        cp[(size_t)ci*K*HW] = v;
    }
}

// ---------------------------------------------------------------------------
// Instance norm: single stats pass (sum+sumsq, float4) + write pass.
// ---------------------------------------------------------------------------
__global__ void __launch_bounds__(256)
instnorm_kernel(const float* __restrict__ in, float* __restrict__ out,
                const float* __restrict__ addsrc, int HW, int relu)
{
    const int bc = blockIdx.x;
    const int HW4 = HW >> 2;
    const float4* p4 = reinterpret_cast<const float4*>(in) + (size_t)bc*HW4;
    float4* q4 = reinterpret_cast<float4*>(out) + (size_t)bc*HW4;
    const float4* a4 = addsrc ?
        reinterpret_cast<const float4*>(addsrc) + (size_t)bc*HW4 : nullptr;

    __shared__ float redS[256];
    __shared__ float redQ[256];
    __shared__ float s_mu, s_rs;
    const int t = threadIdx.x;

    float s = 0.f, q = 0.f;
    for (int i = t; i < HW4; i += 256) {
        const float4 v = p4[i];
        s += v.x + v.y + v.z + v.w;
        q += v.x*v.x + v.y*v.y + v.z*v.z + v.w*v.w;
    }
    redS[t] = s; redQ[t] = q; __syncthreads();
    for (int o = 128; o > 0; o >>= 1) {
        if (t < o) { redS[t] += redS[t+o]; redQ[t] += redQ[t+o]; }
        __syncthreads();
    }
    if (t == 0) {
        const float mu = redS[0] / (float)HW;
        float var = redQ[0] / (float)HW - mu*mu;
        var = fmaxf(var, 0.f);
        s_mu = mu;
        s_rs = rsqrtf(var + 1e-5f);
    }
    __syncthreads();
    const float mu = s_mu;
    const float rs = s_rs;

    for (int i = t; i < HW4; i += 256) {
        float4 v = p4[i];
        v.x = (v.x - mu)*rs; v.y = (v.y - mu)*rs;
        v.z = (v.z - mu)*rs; v.w = (v.w - mu)*rs;
        if (relu) {
            v.x = fmaxf(v.x, 0.f); v.y = fmaxf(v.y, 0.f);
            v.z = fmaxf(v.z, 0.f); v.w = fmaxf(v.w, 0.f);
        }
        if (a4) {
            const float4 a = a4[i];
            v.x += a.x; v.y += a.y; v.z += a.z; v.w += a.w;
        }
        q4[i] = v;
    }
}

// ---------------------------------------------------------------------------
// Launch
// ---------------------------------------------------------------------------
extern "C" void kernel_launch(void* const* d_in, const int* in_sizes, int n_in,
                              void* d_out, int out_size)
{
    const float* x      = (const float*)d_in[0];
    const float* w_off1 = (const float*)d_in[1];
    const float* b_off1 = (const float*)d_in[2];
    const float* w1     = (const float*)d_in[3];
    const float* b1     = (const float*)d_in[4];
    const float* w_off2 = (const float*)d_in[5];
    const float* b_off2 = (const float*)d_in[6];
    const float* w2     = (const float*)d_in[7];
    const float* b2     = (const float*)d_in[8];
    const float* w_off3 = (const float*)d_in[9];
    const float* b_off3 = (const float*)d_in[10];
    const float* w3     = (const float*)d_in[11];
    const float* b3     = (const float*)d_in[12];
    const float* rw0a   = (const float*)d_in[13];
    const float* rb0a   = (const float*)d_in[14];
    const float* rw0b   = (const float*)d_in[15];
    const float* rb0b   = (const float*)d_in[16];
    const float* rw1a   = (const float*)d_in[17];
    const float* rb1a   = (const float*)d_in[18];
    const float* rw1b   = (const float*)d_in[19];
    const float* rb1b   = (const float*)d_in[20];

    float* out = (float*)d_out;
    float* out_h  = out;                                   // [16,256,32,32]
    float* out_s2 = out + 16*256*32*32;                    // [16,128,64,64]
    float* out_s3 = out + 16*256*32*32 + 16*128*64*64;     // [16,256,32,32]

    float *om1,*col1,*t1,*om2,*col2,*t2,*om3,*col3,*t3,*ybuf,*cvb,*hbuf;
    cudaGetSymbolAddress((void**)&om1,  g_om1);
    cudaGetSymbolAddress((void**)&col1, g_col1);
    cudaGetSymbolAddress((void**)&t1,   g_t1);
    cudaGetSymbolAddress((void**)&om2,  g_om2);
    cudaGetSymbolAddress((void**)&col2, g_col2);
    cudaGetSymbolAddress((void**)&t2,   g_t2);
    cudaGetSymbolAddress((void**)&om3,  g_om3);
    cudaGetSymbolAddress((void**)&col3, g_col3);
    cudaGetSymbolAddress((void**)&t3,   g_t3);
    cudaGetSymbolAddress((void**)&ybuf, g_y);
    cudaGetSymbolAddress((void**)&cvb,  g_cv);
    cudaGetSymbolAddress((void**)&hbuf, g_h);

    constexpr int S64   = smemBytes(64, 0);    // 65536
    constexpr int S128  = smemBytes(128, 0);   // 81920
    constexpr int S128R = smemBytes(128, 9);   // 81920 + 4608 = 86528

    auto setmax = [](const void* f, int bytes){
        cudaFuncSetAttribute(f, cudaFuncAttributeMaxDynamicSharedMemorySize, bytes);
    };
    setmax((const void*)conv_mma<3,128,128,7,7,1,3,128,128,0,64>,     S64);
    setmax((const void*)conv_mma<147,128,128,1,1,1,0,128,128,0,64>,   S64);
    setmax((const void*)conv_mma<64,128,128,4,4,2,1,64,64,0,64>,      S64);
    setmax((const void*)conv_mma<1024,64,64,1,1,1,0,64,64,0,128>,     S128);
    setmax((const void*)conv_mma<128,64,64,4,4,2,1,32,32,0,64>,       S64);
    setmax((const void*)conv_mma<2048,32,32,1,1,1,0,32,32,0,128>,     S128);
    setmax((const void*)conv_mma<256,32,32,3,3,1,1,32,32,1,128>,      S128R);

    // ------------------ Stage 1: 3 -> 64, 7x7, s1 p3, 128x128 ------------------
    {
        conv_mma<3,128,128,7,7,1,3,128,128,0,64>
            <<<dim3(2048, 3), 256, S64>>>(x, w_off1, b_off1, om1, 147);

        const int tot = 16*49*128*128;
        deform_sample_kernel<3,128,128,7,7,1,3,128,128>
            <<<(tot+255)/256, 256>>>(x, om1, col1);

        conv_mma<147,128,128,1,1,1,0,128,128,0,64>
            <<<dim3(2048, 1), 256, S64>>>(col1, w1, b1, t1, 64);

        instnorm_kernel<<<16*64, 256>>>(t1, t1, nullptr, 128*128, 1);
    }

    // ------------------ Stage 2: 64 -> 128, 4x4, s2 p1, -> 64x64 ---------------
    {
        conv_mma<64,128,128,4,4,2,1,64,64,0,64>
            <<<dim3(512, 1), 256, S64>>>(t1, w_off2, b_off2, om2, 48);

        const int tot = 16*16*64*64;
        deform_sample_kernel<64,128,128,4,4,2,1,64,64>
            <<<(tot+255)/256, 256>>>(t1, om2, col2);

        conv_mma<1024,64,64,1,1,1,0,64,64,0,128>
            <<<dim3(512, 1), 256, S128>>>(col2, w2, b2, t2, 128);

        instnorm_kernel<<<16*128, 256>>>(t2, out_s2, nullptr, 64*64, 1);   // skip2
    }

    // ------------------ Stage 3: 128 -> 256, 4x4, s2 p1, -> 32x32 --------------
    {
        conv_mma<128,64,64,4,4,2,1,32,32,0,64>
            <<<dim3(128, 1), 256, S64>>>(out_s2, w_off3, b_off3, om3, 48);

        const int tot = 16*16*32*32;
        deform_sample_kernel<128,64,64,4,4,2,1,32,32>
            <<<(tot+255)/256, 256>>>(out_s2, om3, col3);

        conv_mma<2048,32,32,1,1,1,0,32,32,0,128>
            <<<dim3(128, 2), 256, S128>>>(col3, w3, b3, t3, 256);

        instnorm_kernel<<<16*256, 256>>>(t3, out_s3, nullptr, 32*32, 1);   // skip3
    }

    // ------------------ Residual blocks on [16,256,32,32] ----------------------
    const dim3 cgrid(128, 2);

    // block 0: input = skip3 (reads d_out region)
    conv_mma<256,32,32,3,3,1,1,32,32,1,128><<<cgrid, 256, S128R>>>(out_s3, rw0a, rb0a, cvb, 256);
    instnorm_kernel<<<16*256, 256>>>(cvb, ybuf, nullptr, 32*32, 1);
    conv_mma<256,32,32,3,3,1,1,32,32,1,128><<<cgrid, 256, S128R>>>(ybuf, rw0b, rb0b, cvb, 256);
    instnorm_kernel<<<16*256, 256>>>(cvb, hbuf, out_s3, 32*32, 0);   // h = skip3 + IN(conv)

    // block 1: input = hbuf
    conv_mma<256,32,32,3,3,1,1,32,32,1,128><<<cgrid, 256, S128R>>>(hbuf, rw1a, rb1a, cvb, 256);
    instnorm_kernel<<<16*256, 256>>>(cvb, ybuf, nullptr, 32*32, 1);
    conv_mma<256,32,32,3,3,1,1,32,32,1,128><<<cgrid, 256, S128R>>>(ybuf, rw1b, rb1b, cvb, 256);
    instnorm_kernel<<<16*256, 256>>>(cvb, out_h, hbuf, 32*32, 0);    // final h
}